// round 9
// baseline (speedup 1.0000x reference)
#include <cuda_runtime.h>
#include <cuda_fp16.h>

// x:   (B=4, 3, H=2048, W=2048) fp32
// LUT: (3, 33, 33, 33) fp32, index = c*33^3 + b*1089 + g*33 + r
#define NPTS   35937            // 33^3
#define ROW    33
#define PLANE  1089
#define HW4    1048576          // 2048*2048/4
#define NVEC   4194304          // B*HW/4 float4 pixel-vecs per plane set
#define THREADS 1024
#define GROUPS  50              // blocks per channel group
#define BLOCKS  (3 * GROUPS)    // 150
#define SMEM_BYTES (NPTS * 4 + 16)   // half2 pair table for ONE channel

extern __shared__ unsigned char smem_raw[];

// Interpolate one pixel for ONE channel using the r-pair table.
// x guaranteed in [0,1) => lattice coords in [0,32) => no clamping needed.
__device__ __forceinline__ float lut_px_1ch(float r, float g, float b,
                                            const __half2* __restrict__ P) {
    float rr = r * 32.0f;
    float gg = g * 32.0f;
    float bb = b * 32.0f;
    float rf = floorf(rr);
    float gf = floorf(gg);
    float bf = floorf(bb);
    float fr = rr - rf;
    float fg = gg - gf;
    float fb = bb - bf;
    int r0 = (int)rf;
    int g0 = (int)gf;
    int b0 = (int)bf;

    int i00 = b0 * PLANE + g0 * ROW + r0;   // (g0,   b0)
    int i10 = i00 + ROW;                    // (g0+1, b0)
    int i01 = i00 + PLANE;                  // (g0,   b0+1)
    int i11 = i01 + ROW;                    // (g0+1, b0+1)

    float2 p00 = __half22float2(P[i00]);
    float2 p10 = __half22float2(P[i10]);
    float2 p01 = __half22float2(P[i01]);
    float2 p11 = __half22float2(P[i11]);

    float v00 = fmaf(fr, p00.y - p00.x, p00.x);
    float v10 = fmaf(fr, p10.y - p10.x, p10.x);
    float v01 = fmaf(fr, p01.y - p01.x, p01.x);
    float v11 = fmaf(fr, p11.y - p11.x, p11.x);

    float v0 = fmaf(fg, v10 - v00, v00);
    float v1 = fmaf(fg, v11 - v01, v01);
    return fmaf(fb, v1 - v0, v0);
}

__global__ void __launch_bounds__(THREADS, 1)
lut3d_chsplit_kernel(const float* __restrict__ x, const float* __restrict__ LUT,
                     float* __restrict__ out) {
    __half2* P = (__half2*)smem_raw;

    const int c    = blockIdx.x % 3;        // output channel this block computes
    const int rank = blockIdx.x / 3;        // 0..GROUPS-1, identical across channels

    // Build this channel's r-pair table: P[i] = {LUT[c,i], LUT[c,i+1]} (fp16).
    // Scalar loads: LUT + c*NPTS is only 4-byte aligned for c=1,2, so no float4.
    const float* Lc = LUT + c * NPTS;
    for (int i = threadIdx.x; i < NPTS; i += THREADS) {
        float v0 = __ldg(&Lc[i]);
        int j = (i + 1 < NPTS) ? i + 1 : i;
        float v1 = __ldg(&Lc[j]);
        P[i] = __floats2half2_rn(v0, v1);
    }
    __syncthreads();

    const float4* __restrict__ x4 = (const float4*)x;
    float4* __restrict__ op = (float4*)out + c * HW4;   // this channel's out plane

    const int stride = GROUPS * THREADS;    // same stride for every channel group

    int v = rank * THREADS + threadIdx.x;
    if (v >= NVEC) return;

    // base(v) = img*3*HW4 + iv = v + img*2*HW4, img = v >> 20
    int base = v + ((v >> 20) << 21);

    // Prologue: load first iteration's pixel vectors.
    float4 pr = x4[base];
    float4 pg = x4[base + HW4];
    float4 pb = x4[base + 2 * HW4];

    while (true) {
        int vn = v + stride;
        bool more = (vn < NVEC);

        // Prefetch next iteration's x while current gathers run.
        int vc = min(vn, NVEC - 1);
        int base_n = vc + ((vc >> 20) << 21);
        float4 nr = x4[base_n];
        float4 ng = x4[base_n + HW4];
        float4 nb = x4[base_n + 2 * HW4];

        float4 o;
        o.x = lut_px_1ch(pr.x, pg.x, pb.x, P);
        o.y = lut_px_1ch(pr.y, pg.y, pb.y, P);
        o.z = lut_px_1ch(pr.z, pg.z, pb.z, P);
        o.w = lut_px_1ch(pr.w, pg.w, pb.w, P);

        op[base] = o;

        if (!more) break;
        v = vn;
        base = base_n;
        pr = nr; pg = ng; pb = nb;
    }
}

extern "C" void kernel_launch(void* const* d_in, const int* in_sizes, int n_in,
                              void* d_out, int out_size) {
    const float* x   = (const float*)d_in[0];
    const float* LUT = (const float*)d_in[1];
    float* out = (float*)d_out;

    cudaFuncSetAttribute(lut3d_chsplit_kernel,
                         cudaFuncAttributeMaxDynamicSharedMemorySize, SMEM_BYTES);
    lut3d_chsplit_kernel<<<BLOCKS, THREADS, SMEM_BYTES>>>(x, LUT, out);
}

// round 10
// speedup vs baseline: 1.0133x; 1.0133x over previous
#include <cuda_runtime.h>
#include <cuda_fp16.h>

// x:   (B=4, 3, H=2048, W=2048) fp32
// LUT: (3, 33, 33, 33) fp32, index = c*33^3 + b*1089 + g*33 + r
#define NPTS   35937            // 33^3
#define ROW    33
#define PLANE  1089
#define HW4    1048576          // 2048*2048/4
#define NVEC   4194304          // B*HW/4 float4 pixel-vecs per plane set
#define THREADS 1024
#define GROUPS  50              // blocks per channel group
#define BLOCKS  (3 * GROUPS)    // 150
#define SMEM_BYTES (NPTS * 4 + 16)   // half2 pair table for ONE channel

extern __shared__ unsigned char smem_raw[];

struct Gather { __half2 p00, p10, p01, p11; float fr, fg, fb; };

// Stage 1: compute indices and issue the 4 LDS.32 gathers for one pixel.
// x guaranteed in [0,1) => lattice coords in [0,32) => no clamping needed.
__device__ __forceinline__ Gather gather_px(float r, float g, float b,
                                            const __half2* __restrict__ P) {
    float rr = r * 32.0f;
    float gg = g * 32.0f;
    float bb = b * 32.0f;
    float rf = floorf(rr);
    float gf = floorf(gg);
    float bf = floorf(bb);
    Gather G;
    G.fr = rr - rf;
    G.fg = gg - gf;
    G.fb = bb - bf;
    int i00 = (int)bf * PLANE + (int)gf * ROW + (int)rf;
    G.p00 = P[i00];
    G.p10 = P[i00 + ROW];
    G.p01 = P[i00 + PLANE];
    G.p11 = P[i00 + PLANE + ROW];
    return G;
}

// Stage 2: pure math, no memory.
__device__ __forceinline__ float lerp_px(const Gather& G) {
    float2 p00 = __half22float2(G.p00);
    float2 p10 = __half22float2(G.p10);
    float2 p01 = __half22float2(G.p01);
    float2 p11 = __half22float2(G.p11);

    float v00 = fmaf(G.fr, p00.y - p00.x, p00.x);
    float v10 = fmaf(G.fr, p10.y - p10.x, p10.x);
    float v01 = fmaf(G.fr, p01.y - p01.x, p01.x);
    float v11 = fmaf(G.fr, p11.y - p11.x, p11.x);

    float v0 = fmaf(G.fg, v10 - v00, v00);
    float v1 = fmaf(G.fg, v11 - v01, v01);
    return fmaf(G.fb, v1 - v0, v0);
}

__global__ void __launch_bounds__(THREADS, 1)
lut3d_chsplit_kernel(const float* __restrict__ x, const float* __restrict__ LUT,
                     float* __restrict__ out) {
    __half2* P = (__half2*)smem_raw;

    const int c    = blockIdx.x % 3;        // output channel this block computes
    const int rank = blockIdx.x / 3;        // 0..GROUPS-1, identical across channels

    // Build this channel's r-pair table: P[i] = {LUT[c,i], LUT[c,i+1]} (fp16).
    // Scalar loads: LUT + c*NPTS is only 4-byte aligned for c=1,2, so no float4.
    const float* Lc = LUT + c * NPTS;
    for (int i = threadIdx.x; i < NPTS; i += THREADS) {
        float v0 = __ldg(&Lc[i]);
        int j = (i + 1 < NPTS) ? i + 1 : i;
        float v1 = __ldg(&Lc[j]);
        P[i] = __floats2half2_rn(v0, v1);
    }
    __syncthreads();

    const float4* __restrict__ x4 = (const float4*)x;
    float4* __restrict__ op = (float4*)out + c * HW4;   // this channel's out plane

    const int stride = GROUPS * THREADS;    // same stride for every channel group

    int v = rank * THREADS + threadIdx.x;
    if (v >= NVEC) return;

    // base(v) = img*3*HW4 + iv = v + img*2*HW4, img = v >> 20
    int base = v + ((v >> 20) << 21);

    // Prologue: load first iteration's pixel vectors.
    float4 pr = x4[base];
    float4 pg = x4[base + HW4];
    float4 pb = x4[base + 2 * HW4];

    while (true) {
        int vn = v + stride;
        bool more = (vn < NVEC);

        // Prefetch next iteration's x while current gathers run.
        int vc = min(vn, NVEC - 1);
        int base_n = vc + ((vc >> 20) << 21);
        float4 nr = x4[base_n];
        float4 ng = x4[base_n + HW4];
        float4 nb = x4[base_n + 2 * HW4];

        // Phase 1: issue ALL 16 gathers back-to-back (max crossbar occupancy).
        Gather g0 = gather_px(pr.x, pg.x, pb.x, P);
        Gather g1 = gather_px(pr.y, pg.y, pb.y, P);
        Gather g2 = gather_px(pr.z, pg.z, pb.z, P);
        Gather g3 = gather_px(pr.w, pg.w, pb.w, P);

        // Phase 2: pure math.
        float4 o;
        o.x = lerp_px(g0);
        o.y = lerp_px(g1);
        o.z = lerp_px(g2);
        o.w = lerp_px(g3);

        op[base] = o;

        if (!more) break;
        v = vn;
        base = base_n;
        pr = nr; pg = ng; pb = nb;
    }
}

extern "C" void kernel_launch(void* const* d_in, const int* in_sizes, int n_in,
                              void* d_out, int out_size) {
    const float* x   = (const float*)d_in[0];
    const float* LUT = (const float*)d_in[1];
    float* out = (float*)d_out;

    cudaFuncSetAttribute(lut3d_chsplit_kernel,
                         cudaFuncAttributeMaxDynamicSharedMemorySize, SMEM_BYTES);
    lut3d_chsplit_kernel<<<BLOCKS, THREADS, SMEM_BYTES>>>(x, LUT, out);
}